// round 14
// baseline (speedup 1.0000x reference)
#include <cuda_runtime.h>
#include <cuda_fp16.h>
#include <math.h>
#include <stdint.h>

#define T 2048
#define H 2048
#define E 32
#define KSEL 6
#define G 8
#define TOPKG 4
#define II 1408
#define IS 2816
#define SCALEF 2.5f
#define NA (T*KSEL)   // 12288 assignments

// ---------------- scratch (allocation-free: __device__ globals) ----------------
__device__ float    g_topk_w[NA];
__device__ int      g_topk_id[NA];
__device__ int      g_cnt[E];
__device__ int      g_off[E];
__device__ int      g_cur[E];
__device__ int      g_alist[NA];
__device__ unsigned g_done;
__device__ __half   g_xh[(size_t)T * H];        // x in fp16 (8 MB)
__device__ __half   g_hh[(size_t)NA * II];      // routed hidden fp16 (~35 MB)
__device__ __half   g_shh[(size_t)T * IS];      // shared hidden fp16 (~12 MB)

// ---------------- helpers ----------------
__device__ __forceinline__ uint32_t smem_u32(const void* p) {
    uint32_t a;
    asm("{ .reg .u64 t; cvta.to.shared.u64 t, %1; cvt.u32.u64 %0, t; }" : "=r"(a) : "l"(p));
    return a;
}
__device__ __forceinline__ uint32_t pk2(float a, float b) {
    __half2 h = __floats2half2_rn(a, b);
    return *(uint32_t*)&h;
}
__device__ __forceinline__ void cpasync16(uint32_t dst, const void* src) {
    asm volatile("cp.async.cg.shared.global [%0], [%1], 16;" :: "r"(dst), "l"(src));
}
__device__ __forceinline__ void cp_commit() {
    asm volatile("cp.async.commit_group;" ::: "memory");
}
__device__ __forceinline__ void cp_wait0() {
    asm volatile("cp.async.wait_group 0;" ::: "memory");
}
__device__ __forceinline__ void ldmx4(uint32_t* r, uint32_t addr) {
    asm volatile("ldmatrix.sync.aligned.m8n8.x4.shared.b16 {%0,%1,%2,%3}, [%4];"
                 : "=r"(r[0]), "=r"(r[1]), "=r"(r[2]), "=r"(r[3]) : "r"(addr));
}
__device__ __forceinline__ void ldmx4t(uint32_t* r, uint32_t addr) {
    asm volatile("ldmatrix.sync.aligned.m8n8.x4.trans.shared.b16 {%0,%1,%2,%3}, [%4];"
                 : "=r"(r[0]), "=r"(r[1]), "=r"(r[2]), "=r"(r[3]) : "r"(addr));
}
__device__ __forceinline__ void mma16(float* d, const uint32_t* a, uint32_t b0, uint32_t b1) {
    asm volatile(
        "mma.sync.aligned.m16n8k16.row.col.f32.f16.f16.f32 "
        "{%0,%1,%2,%3}, {%4,%5,%6,%7}, {%8,%9}, {%0,%1,%2,%3};"
        : "+f"(d[0]), "+f"(d[1]), "+f"(d[2]), "+f"(d[3])
        : "r"(a[0]), "r"(a[1]), "r"(a[2]), "r"(a[3]), "r"(b0), "r"(b1));
}
__device__ __forceinline__ float silu(float g) { return g / (1.f + expf(-g)); }

// ---------------- small kernels ----------------
__global__ void xhalf_kernel(const float* __restrict__ x, float* __restrict__ out) {
    int idx = blockIdx.x * blockDim.x + threadIdx.x;
    if (blockIdx.x == 0 && threadIdx.x < E) g_cnt[threadIdx.x] = 0;
    if (blockIdx.x == 0 && threadIdx.x == 0) g_done = 0;
    if (idx >= (T * H) / 4) return;
    float4 v = *(const float4*)(x + (size_t)idx * 4);
    uint2 o = make_uint2(pk2(v.x, v.y), pk2(v.z, v.w));
    *(uint2*)(g_xh + (size_t)idx * 4) = o;
    *(float4*)(out + (size_t)idx * 4) = make_float4(0.f, 0.f, 0.f, 0.f);
}

__global__ void router_kernel(const float* __restrict__ x,
                              const float* __restrict__ gw,
                              const float* __restrict__ gb) {
    int t = blockIdx.x;
    __shared__ float xs[H];
    __shared__ float logit[E];
    for (int i = threadIdx.x; i < H; i += blockDim.x) xs[i] = x[(size_t)t * H + i];
    __syncthreads();
    int warp = threadIdx.x >> 5, lane = threadIdx.x & 31;
    for (int e = warp; e < E; e += 4) {
        const float* w = gw + (size_t)e * H;
        float s = 0.f;
        for (int i = lane; i < H; i += 32) s += xs[i] * w[i];
        #pragma unroll
        for (int o = 16; o; o >>= 1) s += __shfl_xor_sync(0xffffffffu, s, o);
        if (lane == 0) logit[e] = s;
    }
    __syncthreads();
    if (threadIdx.x == 0) {
        float sc[E], ss[E];
        #pragma unroll
        for (int e = 0; e < E; e++) {
            float s = 1.f / (1.f + expf(-logit[e]));
            ss[e] = s;
            sc[e] = s + gb[e];
        }
        float gsc[G];
        #pragma unroll
        for (int g = 0; g < G; g++) {
            float m1 = -1e30f, m2 = -1e30f;
            #pragma unroll
            for (int j = 0; j < 4; j++) {
                float v = sc[g * 4 + j];
                if (v > m1) { m2 = m1; m1 = v; } else if (v > m2) m2 = v;
            }
            gsc[g] = m1 + m2;
        }
        bool gsel[G];
        #pragma unroll
        for (int g = 0; g < G; g++) gsel[g] = false;
        for (int r = 0; r < TOPKG; r++) {
            int best = -1; float bv = -1e30f;
            for (int g = 0; g < G; g++)
                if (!gsel[g] && gsc[g] > bv) { bv = gsc[g]; best = g; }
            gsel[best] = true;
        }
        bool esel[E];
        #pragma unroll
        for (int e = 0; e < E; e++) esel[e] = false;
        int ids[KSEL];
        for (int r = 0; r < KSEL; r++) {
            int best = -1; float bv = -1e30f;
            for (int e = 0; e < E; e++) {
                if (esel[e] || !gsel[e >> 2]) continue;
                if (sc[e] > bv) { bv = sc[e]; best = e; }
            }
            esel[best] = true; ids[r] = best;
        }
        float w[KSEL], wsum = 0.f;
        for (int r = 0; r < KSEL; r++) { w[r] = ss[ids[r]]; wsum += w[r]; }
        float inv = 1.f / wsum;
        for (int r = 0; r < KSEL; r++) {
            g_topk_w[t * KSEL + r] = w[r] * inv;
            g_topk_id[t * KSEL + r] = ids[r];
            atomicAdd(&g_cnt[ids[r]], 1);
        }
        __threadfence();
        unsigned prev = atomicAdd(&g_done, 1u);
        if (prev == gridDim.x - 1) {
            int run = 0;
            for (int e = 0; e < E; e++) {
                g_off[e] = run;
                g_cur[e] = run;
                run += g_cnt[e];
            }
        }
    }
}

__global__ void fill_kernel() {
    int a = blockIdx.x * blockDim.x + threadIdx.x;
    if (a >= NA) return;
    int e = g_topk_id[a];
    int pos = atomicAdd(&g_cur[e], 1);
    g_alist[pos] = a;
}

// =====================================================================
// MERGED gate_up GEMM + silu*mul(*wt) -> fp16 hidden. (R9 config)
// blockIdx.z in [0,32]: z<32 routed expert z, z==32 shared expert.
// B smem [k][n] (272B stride) + ldmatrix.trans. Block 128x128; K-chunk 32.
// stsB for chunk c+1 interleaved between the ks MMA batches of chunk c.
// =====================================================================
#define ASTG_FA 10240        // A stage: 128 * 80
#define BSTG_F  17408        // B stage: 2 tiles * 32 * 272
#define BOFF_F  (2*ASTG_FA)
#define SMEM_F  (2*ASTG_FA + 2*BSTG_F + 2048)

__global__ void __launch_bounds__(256, 1)
gemm_gateup(const float* __restrict__ w1, const float* __restrict__ sw1)
{
    const bool routed = (blockIdx.z < 32);
    const int NPER = routed ? II : IS;
    const int LDB  = 2 * NPER;
    constexpr int NC = H / 32;

    if ((int)(blockIdx.y * 128) >= NPER) return;

    extern __shared__ char smem[];
    const uint32_t sbase = smem_u32(smem);
    char* meta = smem + 2 * ASTG_FA + 2 * BSTG_F;
    const __half** rowptr = (const __half**)meta;     // 128 ptrs
    int* aidx = (int*)(meta + 1024);                  // 128 ints

    int n, off = 0;
    const float* Bb;
    if (routed) {
        int e = blockIdx.z;
        n = g_cnt[e]; off = g_off[e];
        if ((int)(blockIdx.x * 128) >= n) return;
        Bb = w1 + (size_t)e * (size_t)H * (2 * II);
    } else { n = T; Bb = sw1; }

    const int row0 = blockIdx.x * 128;
    const int col0 = blockIdx.y * 128;
    const int tid = threadIdx.x;
    const int nv = routed ? min(128, n - row0) : 128;

    if (tid < 128) {
        int gr = row0 + tid;
        int a = -1;
        if (routed && gr < n) a = g_alist[off + gr];
        int aa = (!routed) ? gr : ((a >= 0 ? a : g_alist[off]) / KSEL);
        rowptr[tid] = g_xh + (size_t)aa * H;
        aidx[tid] = a;
    }
    __syncthreads();

    const int lane = tid & 31, wid = tid >> 5;
    const int wm = wid >> 2, wn = wid & 3;
    const int gg = lane >> 2, t4 = lane & 3;

    float4 bF[8];
    float accg[4][4][4] = {}, accu[4][4][4] = {};

    auto cpA = [&](int k0, int s) {
        #pragma unroll
        for (int r = 0; r < 2; r++) {
            int u = tid + 256 * r;
            int m = u >> 2, kq = u & 3;
            cpasync16(sbase + s * ASTG_FA + m * 80 + kq * 16, rowptr[m] + k0 + kq * 8);
        }
    };
    auto ldgB = [&](int k0) {
        #pragma unroll
        for (int r = 0; r < 8; r++) {
            int u = tid + 256 * r;
            int tile = u >> 10;            // 0 = gate, 1 = up
            int k = (u >> 5) & 31, ng = u & 31;
            const float* gp = Bb + (size_t)(k0 + k) * LDB + tile * NPER + col0 + ng * 4;
            bF[r] = *(const float4*)gp;
        }
    };
    // half h of the B store (r in [h*4, h*4+4))
    auto stsB_half = [&](int s, int h) {
        char* B_ = smem + BOFF_F + s * BSTG_F;
        #pragma unroll
        for (int r = h * 4; r < h * 4 + 4; r++) {
            int u = tid + 256 * r;
            int tile = u >> 10;
            int k = (u >> 5) & 31, ng = u & 31;
            *(uint2*)(B_ + tile * 8704 + k * 272 + ng * 8) =
                make_uint2(pk2(bF[r].x, bF[r].y), pk2(bF[r].z, bF[r].w));
        }
    };
    const int lrA = (lane & 7) + ((lane >> 3) & 1) * 8;
    const int lkA = (lane >> 4) * 8;
    const int kBo = (lane & 7) + ((lane >> 3) & 1) * 8;
    const int nBo = (lane >> 4) * 8;
    // one ks batch of MMAs for chunk in stage s
    auto comp_ks = [&](int s, int ks) {
        const uint32_t Ab = sbase + s * ASTG_FA;
        const uint32_t Bgb = sbase + BOFF_F + s * BSTG_F;
        const uint32_t Bub = Bgb + 8704;
        if (wm * 64 >= nv) return;
        const int kh = ks * 16;
        uint32_t af[4][4];
        #pragma unroll
        for (int mt = 0; mt < 4; mt++)
            if (wm * 64 + mt * 16 < nv)
                ldmx4(af[mt], Ab + (wm * 64 + mt * 16 + lrA) * 80 + (kh + lkA) * 2);
        uint32_t bfg[2][4], bfu[2][4];
        #pragma unroll
        for (int np = 0; np < 2; np++) {
            uint32_t co = (wn * 32 + np * 16 + nBo) * 2;
            ldmx4t(bfg[np], Bgb + (kh + kBo) * 272 + co);
            ldmx4t(bfu[np], Bub + (kh + kBo) * 272 + co);
        }
        #pragma unroll
        for (int mt = 0; mt < 4; mt++) {
            if (wm * 64 + mt * 16 >= nv) continue;
            #pragma unroll
            for (int nt = 0; nt < 4; nt++) {
                mma16(accg[mt][nt], af[mt], bfg[nt >> 1][(nt & 1) * 2], bfg[nt >> 1][(nt & 1) * 2 + 1]);
                mma16(accu[mt][nt], af[mt], bfu[nt >> 1][(nt & 1) * 2], bfu[nt >> 1][(nt & 1) * 2 + 1]);
            }
        }
    };

    cpA(0, 0); cp_commit();
    ldgB(0);
    stsB_half(0, 0); stsB_half(0, 1);
    cp_wait0();
    __syncthreads();
    for (int c = 0; c < NC; c++) {
        const int s = c & 1, s1 = (c + 1) & 1;
        const bool more = (c + 1 < NC);
        if (more) {
            cpA((c + 1) * 32, s1); cp_commit();
            ldgB((c + 1) * 32);
        }
        comp_ks(s, 0);
        if (more) stsB_half(s1, 0);     // interleave stores between MMA batches
        comp_ks(s, 1);
        if (more) stsB_half(s1, 1);
        cp_wait0();
        __syncthreads();
    }

    // epilogue: h = silu(g)*u*wt  -> fp16
    #pragma unroll
    for (int mt = 0; mt < 4; mt++) {
        #pragma unroll
        for (int hf = 0; hf < 2; hf++) {
            int r = wm * 64 + mt * 16 + gg + hf * 8;
            __half* drow = nullptr;
            float wt = 1.f;
            if (!routed) drow = g_shh + (size_t)(row0 + r) * IS + col0;
            else {
                int a = aidx[r];
                if (a >= 0) { drow = g_hh + (size_t)a * II + col0; wt = g_topk_w[a]; }
            }
            if (drow) {
                #pragma unroll
                for (int nt = 0; nt < 4; nt++) {
                    int cc = wn * 32 + nt * 8 + t4 * 2;
                    float g0 = accg[mt][nt][hf * 2],     u0 = accu[mt][nt][hf * 2];
                    float g1 = accg[mt][nt][hf * 2 + 1], u1 = accu[mt][nt][hf * 2 + 1];
                    *(__half2*)(drow + cc) = __floats2half2_rn(silu(g0) * u0 * wt, silu(g1) * u1 * wt);
                }
            }
        }
    }
}

// =====================================================================
// MERGED down-proj GEMM: z<32 routed (K=II), z==32 shared (K=IS).
// out pre-zeroed; both paths atomicAdd (routed scaled by 2.5).
// Block 128x128, K-chunk 64. stsB quarters interleaved between ks batches.
// =====================================================================
#define ASTG_DA 18432        // A stage: 128 * 144
#define BSTG_D  17408        // B stage: 64 * 272
#define BOFF_D  (2*ASTG_DA)
#define SMEM_D  (2*ASTG_DA + 2*BSTG_D + 2048)

__global__ void __launch_bounds__(256, 1)
gemm_down(const float* __restrict__ w2, const float* __restrict__ sw2, float* __restrict__ Dout)
{
    const bool routed = (blockIdx.z < 32);
    const int KTOT = routed ? II : IS;
    const int NCr  = KTOT / 64;

    extern __shared__ char smem[];
    const uint32_t sbase = smem_u32(smem);
    char* meta = smem + 2 * ASTG_DA + 2 * BSTG_D;
    const __half** rowptr = (const __half**)meta;
    int* aidx = (int*)(meta + 1024);

    int n, off = 0;
    const float* Bb;
    if (routed) {
        int e = blockIdx.z;
        n = g_cnt[e]; off = g_off[e];
        if ((int)(blockIdx.x * 128) >= n) return;
        Bb = w2 + (size_t)e * (size_t)II * H;
    } else { n = T; Bb = sw2; }

    const int row0 = blockIdx.x * 128;
    const int col0 = blockIdx.y * 128;
    const int tid = threadIdx.x;
    const int nv = routed ? min(128, n - row0) : 128;

    if (tid < 128) {
        int gr = row0 + tid;
        int a = -1;
        const __half* p;
        if (!routed) p = g_shh + (size_t)gr * IS;
        else {
            if (gr < n) a = g_alist[off + gr];
            int aa = a >= 0 ? a : g_alist[off];
            p = g_hh + (size_t)aa * II;
        }
        rowptr[tid] = p;
        aidx[tid] = a;
    }
    __syncthreads();

    const int lane = tid & 31, wid = tid >> 5;
    const int wm = wid >> 2, wn = wid & 3;
    const int gg = lane >> 2, t4 = lane & 3;

    float4 bF[8];
    float acc[4][4][4] = {};

    auto cpA = [&](int k0, int s) {
        #pragma unroll
        for (int r = 0; r < 4; r++) {
            int u = tid + 256 * r;
            int m = u >> 3, kq = u & 7;
            cpasync16(sbase + s * ASTG_DA + m * 144 + kq * 16, rowptr[m] + k0 + kq * 8);
        }
    };
    auto ldgB = [&](int k0) {
        #pragma unroll
        for (int r = 0; r < 8; r++) {
            int u = tid + 256 * r;
            int k = u >> 5, ng = u & 31;
            bF[r] = *(const float4*)(Bb + (size_t)(k0 + k) * H + col0 + ng * 4);
        }
    };
    // quarter q of the B store (r in [q*2, q*2+2))
    auto stsB_q = [&](int s, int q) {
        char* B_ = smem + BOFF_D + s * BSTG_D;
        #pragma unroll
        for (int r = q * 2; r < q * 2 + 2; r++) {
            int u = tid + 256 * r;
            int k = u >> 5, ng = u & 31;
            *(uint2*)(B_ + k * 272 + ng * 8) =
                make_uint2(pk2(bF[r].x, bF[r].y), pk2(bF[r].z, bF[r].w));
        }
    };
    const int lrA = (lane & 7) + ((lane >> 3) & 1) * 8;
    const int lkA = (lane >> 4) * 8;
    const int kBo = (lane & 7) + ((lane >> 3) & 1) * 8;
    const int nBo = (lane >> 4) * 8;
    auto comp_ks = [&](int s, int ks) {
        const uint32_t Ab = sbase + s * ASTG_DA;
        const uint32_t Bbs = sbase + BOFF_D + s * BSTG_D;
        if (wm * 64 >= nv) return;
        const int kh = ks * 16;
        uint32_t af[4][4];
        #pragma unroll
        for (int mt = 0; mt < 4; mt++)
            if (wm * 64 + mt * 16 < nv)
                ldmx4(af[mt], Ab + (wm * 64 + mt * 16 + lrA) * 144 + (kh + lkA) * 2);
        uint32_t bf[2][4];
        #pragma unroll
        for (int np = 0; np < 2; np++)
            ldmx4t(bf[np], Bbs + (kh + kBo) * 272 + (wn * 32 + np * 16 + nBo) * 2);
        #pragma unroll
        for (int mt = 0; mt < 4; mt++) {
            if (wm * 64 + mt * 16 >= nv) continue;
            #pragma unroll
            for (int nt = 0; nt < 4; nt++)
                mma16(acc[mt][nt], af[mt], bf[nt >> 1][(nt & 1) * 2], bf[nt >> 1][(nt & 1) * 2 + 1]);
        }
    };

    cpA(0, 0); cp_commit();
    ldgB(0);
    stsB_q(0, 0); stsB_q(0, 1); stsB_q(0, 2); stsB_q(0, 3);
    cp_wait0();
    __syncthreads();
    for (int c = 0; c < NCr; c++) {
        const int s = c & 1, s1 = (c + 1) & 1;
        const bool more = (c + 1 < NCr);
        if (more) {
            cpA((c + 1) * 64, s1); cp_commit();
            ldgB((c + 1) * 64);
        }
        comp_ks(s, 0);
        if (more) stsB_q(s1, 0);
        comp_ks(s, 1);
        if (more) stsB_q(s1, 1);
        comp_ks(s, 2);
        if (more) stsB_q(s1, 2);
        comp_ks(s, 3);
        if (more) stsB_q(s1, 3);
        cp_wait0();
        __syncthreads();
    }

    const float scale = routed ? SCALEF : 1.f;
    #pragma unroll
    for (int mt = 0; mt < 4; mt++) {
        #pragma unroll
        for (int hf = 0; hf < 2; hf++) {
            int r = wm * 64 + mt * 16 + gg + hf * 8;
            float* drow = nullptr;
            if (!routed) drow = Dout + (size_t)(row0 + r) * H + col0;
            else {
                int a = aidx[r];
                if (a >= 0) drow = Dout + (size_t)(a / KSEL) * H + col0;
            }
            if (drow) {
                #pragma unroll
                for (int nt = 0; nt < 4; nt++) {
                    int cc = wn * 32 + nt * 8 + t4 * 2;
                    atomicAdd(drow + cc,     scale * acc[mt][nt][hf * 2]);
                    atomicAdd(drow + cc + 1, scale * acc[mt][nt][hf * 2 + 1]);
                }
            }
        }
    }
}

// ---------------- launch ----------------
extern "C" void kernel_launch(void* const* d_in, const int* in_sizes, int n_in,
                              void* d_out, int out_size) {
    const float* x   = (const float*)d_in[0];
    const float* gw  = (const float*)d_in[1];
    const float* gb  = (const float*)d_in[2];
    const float* w1  = (const float*)d_in[3];
    const float* w2  = (const float*)d_in[4];
    const float* sw1 = (const float*)d_in[5];
    const float* sw2 = (const float*)d_in[6];
    float* out = (float*)d_out;

    cudaFuncSetAttribute(gemm_gateup, cudaFuncAttributeMaxDynamicSharedMemorySize, SMEM_F);
    cudaFuncSetAttribute(gemm_down,   cudaFuncAttributeMaxDynamicSharedMemorySize, SMEM_D);

    xhalf_kernel<<<((T * H / 4) + 255) / 256, 256>>>(x, out);
    router_kernel<<<T, 128>>>(x, gw, gb);
    fill_kernel<<<(NA + 255) / 256, 256>>>();

    // merged gate_up: z<32 routed experts, z==32 shared expert
    gemm_gateup<<<dim3(16, IS / 128, E + 1), 256, SMEM_F>>>(w1, sw1);
    // merged down-proj: all paths atomicAdd into pre-zeroed out
    gemm_down<<<dim3(16, H / 128, E + 1), 256, SMEM_D>>>(w2, sw2, out);
}

// round 15
// speedup vs baseline: 1.1347x; 1.1347x over previous
#include <cuda_runtime.h>
#include <cuda_fp16.h>
#include <math.h>
#include <stdint.h>

#define T 2048
#define H 2048
#define E 32
#define KSEL 6
#define G 8
#define TOPKG 4
#define II 1408
#define IS 2816
#define SCALEF 2.5f
#define NA (T*KSEL)   // 12288 assignments

// ---------------- scratch (allocation-free: __device__ globals) ----------------
__device__ float    g_topk_w[NA];
__device__ int      g_topk_id[NA];
__device__ int      g_cnt[E];
__device__ int      g_off[E];
__device__ int      g_cur[E];
__device__ int      g_alist[NA];
__device__ unsigned g_done;
__device__ __half   g_xh[(size_t)T * H];        // x in fp16 (8 MB)
__device__ __half   g_hh[(size_t)NA * II];      // routed hidden fp16 (~35 MB)
__device__ __half   g_shh[(size_t)T * IS];      // shared hidden fp16 (~12 MB)

// ---------------- helpers ----------------
__device__ __forceinline__ uint32_t smem_u32(const void* p) {
    uint32_t a;
    asm("{ .reg .u64 t; cvta.to.shared.u64 t, %1; cvt.u32.u64 %0, t; }" : "=r"(a) : "l"(p));
    return a;
}
__device__ __forceinline__ uint32_t pk2(float a, float b) {
    __half2 h = __floats2half2_rn(a, b);
    return *(uint32_t*)&h;
}
__device__ __forceinline__ void cpasync16(uint32_t dst, const void* src) {
    asm volatile("cp.async.cg.shared.global [%0], [%1], 16;" :: "r"(dst), "l"(src));
}
__device__ __forceinline__ void cp_commit() {
    asm volatile("cp.async.commit_group;" ::: "memory");
}
__device__ __forceinline__ void cp_wait0() {
    asm volatile("cp.async.wait_group 0;" ::: "memory");
}
__device__ __forceinline__ void ldmx4(uint32_t* r, uint32_t addr) {
    asm volatile("ldmatrix.sync.aligned.m8n8.x4.shared.b16 {%0,%1,%2,%3}, [%4];"
                 : "=r"(r[0]), "=r"(r[1]), "=r"(r[2]), "=r"(r[3]) : "r"(addr));
}
__device__ __forceinline__ void ldmx4t(uint32_t* r, uint32_t addr) {
    asm volatile("ldmatrix.sync.aligned.m8n8.x4.trans.shared.b16 {%0,%1,%2,%3}, [%4];"
                 : "=r"(r[0]), "=r"(r[1]), "=r"(r[2]), "=r"(r[3]) : "r"(addr));
}
__device__ __forceinline__ void mma16(float* d, const uint32_t* a, uint32_t b0, uint32_t b1) {
    asm volatile(
        "mma.sync.aligned.m16n8k16.row.col.f32.f16.f16.f32 "
        "{%0,%1,%2,%3}, {%4,%5,%6,%7}, {%8,%9}, {%0,%1,%2,%3};"
        : "+f"(d[0]), "+f"(d[1]), "+f"(d[2]), "+f"(d[3])
        : "r"(a[0]), "r"(a[1]), "r"(a[2]), "r"(a[3]), "r"(b0), "r"(b1));
}
__device__ __forceinline__ float silu(float g) { return g / (1.f + expf(-g)); }

// ---------------- small kernels ----------------
__global__ void xhalf_kernel(const float* __restrict__ x, float* __restrict__ out) {
    int idx = blockIdx.x * blockDim.x + threadIdx.x;
    if (blockIdx.x == 0 && threadIdx.x < E) g_cnt[threadIdx.x] = 0;
    if (blockIdx.x == 0 && threadIdx.x == 0) g_done = 0;
    if (idx >= (T * H) / 4) return;
    float4 v = *(const float4*)(x + (size_t)idx * 4);
    uint2 o = make_uint2(pk2(v.x, v.y), pk2(v.z, v.w));
    *(uint2*)(g_xh + (size_t)idx * 4) = o;
    *(float4*)(out + (size_t)idx * 4) = make_float4(0.f, 0.f, 0.f, 0.f);
}

__global__ void router_kernel(const float* __restrict__ x,
                              const float* __restrict__ gw,
                              const float* __restrict__ gb) {
    int t = blockIdx.x;
    __shared__ float xs[H];
    __shared__ float logit[E];
    for (int i = threadIdx.x; i < H; i += blockDim.x) xs[i] = x[(size_t)t * H + i];
    __syncthreads();
    int warp = threadIdx.x >> 5, lane = threadIdx.x & 31;
    for (int e = warp; e < E; e += 4) {
        const float* w = gw + (size_t)e * H;
        float s = 0.f;
        for (int i = lane; i < H; i += 32) s += xs[i] * w[i];
        #pragma unroll
        for (int o = 16; o; o >>= 1) s += __shfl_xor_sync(0xffffffffu, s, o);
        if (lane == 0) logit[e] = s;
    }
    __syncthreads();
    if (threadIdx.x == 0) {
        float sc[E], ss[E];
        #pragma unroll
        for (int e = 0; e < E; e++) {
            float s = 1.f / (1.f + expf(-logit[e]));
            ss[e] = s;
            sc[e] = s + gb[e];
        }
        float gsc[G];
        #pragma unroll
        for (int g = 0; g < G; g++) {
            float m1 = -1e30f, m2 = -1e30f;
            #pragma unroll
            for (int j = 0; j < 4; j++) {
                float v = sc[g * 4 + j];
                if (v > m1) { m2 = m1; m1 = v; } else if (v > m2) m2 = v;
            }
            gsc[g] = m1 + m2;
        }
        bool gsel[G];
        #pragma unroll
        for (int g = 0; g < G; g++) gsel[g] = false;
        for (int r = 0; r < TOPKG; r++) {
            int best = -1; float bv = -1e30f;
            for (int g = 0; g < G; g++)
                if (!gsel[g] && gsc[g] > bv) { bv = gsc[g]; best = g; }
            gsel[best] = true;
        }
        bool esel[E];
        #pragma unroll
        for (int e = 0; e < E; e++) esel[e] = false;
        int ids[KSEL];
        for (int r = 0; r < KSEL; r++) {
            int best = -1; float bv = -1e30f;
            for (int e = 0; e < E; e++) {
                if (esel[e] || !gsel[e >> 2]) continue;
                if (sc[e] > bv) { bv = sc[e]; best = e; }
            }
            esel[best] = true; ids[r] = best;
        }
        float w[KSEL], wsum = 0.f;
        for (int r = 0; r < KSEL; r++) { w[r] = ss[ids[r]]; wsum += w[r]; }
        float inv = 1.f / wsum;
        for (int r = 0; r < KSEL; r++) {
            g_topk_w[t * KSEL + r] = w[r] * inv;
            g_topk_id[t * KSEL + r] = ids[r];
            atomicAdd(&g_cnt[ids[r]], 1);
        }
        __threadfence();
        unsigned prev = atomicAdd(&g_done, 1u);
        if (prev == gridDim.x - 1) {
            int run = 0;
            for (int e = 0; e < E; e++) {
                g_off[e] = run;
                g_cur[e] = run;
                run += g_cnt[e];
            }
        }
    }
}

__global__ void fill_kernel() {
    int a = blockIdx.x * blockDim.x + threadIdx.x;
    if (a >= NA) return;
    int e = g_topk_id[a];
    int pos = atomicAdd(&g_cur[e], 1);
    g_alist[pos] = a;
}

// =====================================================================
// MERGED gate_up GEMM + silu*mul(*wt) -> fp16 hidden. (R9 inner loop)
// Grid (16, 11, 34): z in {0,1} = shared expert (col tiles z*11+y of 22),
// z>=2 = routed expert z-2 (col tiles y of 11). Shared launches FIRST.
// No dead blocks. Block 128x128; K-chunk 32.
// =====================================================================
#define ASTG_FA 10240        // A stage: 128 * 80
#define BSTG_F  17408        // B stage: 2 tiles * 32 * 272
#define BOFF_F  (2*ASTG_FA)
#define SMEM_F  (2*ASTG_FA + 2*BSTG_F + 2048)

__global__ void __launch_bounds__(256, 1)
gemm_gateup(const float* __restrict__ w1, const float* __restrict__ sw1)
{
    const bool routed = (blockIdx.z >= 2);
    const int NPER = routed ? II : IS;
    const int LDB  = 2 * NPER;
    constexpr int NC = H / 32;

    extern __shared__ char smem[];
    const uint32_t sbase = smem_u32(smem);
    char* meta = smem + 2 * ASTG_FA + 2 * BSTG_F;
    const __half** rowptr = (const __half**)meta;     // 128 ptrs
    int* aidx = (int*)(meta + 1024);                  // 128 ints

    int n, off = 0, colTile;
    const float* Bb;
    if (routed) {
        int e = blockIdx.z - 2;
        n = g_cnt[e]; off = g_off[e];
        if ((int)(blockIdx.x * 128) >= n) return;
        Bb = w1 + (size_t)e * (size_t)H * (2 * II);
        colTile = blockIdx.y;                 // 0..10
    } else {
        n = T; Bb = sw1;
        colTile = blockIdx.z * 11 + blockIdx.y;   // 0..21
    }

    const int row0 = blockIdx.x * 128;
    const int col0 = colTile * 128;
    const int tid = threadIdx.x;
    const int nv = routed ? min(128, n - row0) : 128;

    if (tid < 128) {
        int gr = row0 + tid;
        int a = -1;
        if (routed && gr < n) a = g_alist[off + gr];
        int aa = (!routed) ? gr : ((a >= 0 ? a : g_alist[off]) / KSEL);
        rowptr[tid] = g_xh + (size_t)aa * H;
        aidx[tid] = a;
    }
    __syncthreads();

    const int lane = tid & 31, wid = tid >> 5;
    const int wm = wid >> 2, wn = wid & 3;
    const int gg = lane >> 2, t4 = lane & 3;

    float4 bF[8];
    float accg[4][4][4] = {}, accu[4][4][4] = {};

    auto cpA = [&](int k0, int s) {
        #pragma unroll
        for (int r = 0; r < 2; r++) {
            int u = tid + 256 * r;
            int m = u >> 2, kq = u & 3;
            cpasync16(sbase + s * ASTG_FA + m * 80 + kq * 16, rowptr[m] + k0 + kq * 8);
        }
    };
    auto ldgB = [&](int k0) {
        #pragma unroll
        for (int r = 0; r < 8; r++) {
            int u = tid + 256 * r;
            int tile = u >> 10;            // 0 = gate, 1 = up
            int k = (u >> 5) & 31, ng = u & 31;
            const float* gp = Bb + (size_t)(k0 + k) * LDB + tile * NPER + col0 + ng * 4;
            bF[r] = *(const float4*)gp;
        }
    };
    auto stsB = [&](int s) {
        char* B_ = smem + BOFF_F + s * BSTG_F;
        #pragma unroll
        for (int r = 0; r < 8; r++) {
            int u = tid + 256 * r;
            int tile = u >> 10;
            int k = (u >> 5) & 31, ng = u & 31;
            *(uint2*)(B_ + tile * 8704 + k * 272 + ng * 8) =
                make_uint2(pk2(bF[r].x, bF[r].y), pk2(bF[r].z, bF[r].w));
        }
    };
    const int lrA = (lane & 7) + ((lane >> 3) & 1) * 8;
    const int lkA = (lane >> 4) * 8;
    const int kBo = (lane & 7) + ((lane >> 3) & 1) * 8;
    const int nBo = (lane >> 4) * 8;
    auto comp = [&](int s) {
        const uint32_t Ab = sbase + s * ASTG_FA;
        const uint32_t Bgb = sbase + BOFF_F + s * BSTG_F;
        const uint32_t Bub = Bgb + 8704;
        if (wm * 64 >= nv) return;
        #pragma unroll
        for (int ks = 0; ks < 2; ks++) {
            const int kh = ks * 16;
            uint32_t af[4][4];
            #pragma unroll
            for (int mt = 0; mt < 4; mt++)
                if (wm * 64 + mt * 16 < nv)
                    ldmx4(af[mt], Ab + (wm * 64 + mt * 16 + lrA) * 80 + (kh + lkA) * 2);
            uint32_t bfg[2][4], bfu[2][4];
            #pragma unroll
            for (int np = 0; np < 2; np++) {
                uint32_t co = (wn * 32 + np * 16 + nBo) * 2;
                ldmx4t(bfg[np], Bgb + (kh + kBo) * 272 + co);
                ldmx4t(bfu[np], Bub + (kh + kBo) * 272 + co);
            }
            #pragma unroll
            for (int mt = 0; mt < 4; mt++) {
                if (wm * 64 + mt * 16 >= nv) continue;
                #pragma unroll
                for (int nt = 0; nt < 4; nt++) {
                    mma16(accg[mt][nt], af[mt], bfg[nt >> 1][(nt & 1) * 2], bfg[nt >> 1][(nt & 1) * 2 + 1]);
                    mma16(accu[mt][nt], af[mt], bfu[nt >> 1][(nt & 1) * 2], bfu[nt >> 1][(nt & 1) * 2 + 1]);
                }
            }
        }
    };

    cpA(0, 0); cp_commit();
    ldgB(0);
    stsB(0);
    cp_wait0();
    __syncthreads();
    for (int c = 0; c < NC; c++) {
        if (c + 1 < NC) {
            cpA((c + 1) * 32, (c + 1) & 1); cp_commit();
            ldgB((c + 1) * 32);
        }
        comp(c & 1);
        if (c + 1 < NC) stsB((c + 1) & 1);
        cp_wait0();
        __syncthreads();
    }

    // epilogue: h = silu(g)*u*wt  -> fp16
    #pragma unroll
    for (int mt = 0; mt < 4; mt++) {
        #pragma unroll
        for (int hf = 0; hf < 2; hf++) {
            int r = wm * 64 + mt * 16 + gg + hf * 8;
            __half* drow = nullptr;
            float wt = 1.f;
            if (!routed) drow = g_shh + (size_t)(row0 + r) * IS + col0;
            else {
                int a = aidx[r];
                if (a >= 0) { drow = g_hh + (size_t)a * II + col0; wt = g_topk_w[a]; }
            }
            if (drow) {
                #pragma unroll
                for (int nt = 0; nt < 4; nt++) {
                    int cc = wn * 32 + nt * 8 + t4 * 2;
                    float g0 = accg[mt][nt][hf * 2],     u0 = accu[mt][nt][hf * 2];
                    float g1 = accg[mt][nt][hf * 2 + 1], u1 = accu[mt][nt][hf * 2 + 1];
                    *(__half2*)(drow + cc) = __floats2half2_rn(silu(g0) * u0 * wt, silu(g1) * u1 * wt);
                }
            }
        }
    }
}

// =====================================================================
// MERGED down-proj GEMM: z==0 shared (K=IS, longest — launches first),
// z>=1 routed expert z-1 (K=II). out pre-zeroed; both paths atomicAdd.
// Block 128x128, K-chunk 64.  (R9 inner loop)
// =====================================================================
#define ASTG_DA 18432        // A stage: 128 * 144
#define BSTG_D  17408        // B stage: 64 * 272
#define BOFF_D  (2*ASTG_DA)
#define SMEM_D  (2*ASTG_DA + 2*BSTG_D + 2048)

__global__ void __launch_bounds__(256, 1)
gemm_down(const float* __restrict__ w2, const float* __restrict__ sw2, float* __restrict__ Dout)
{
    const bool routed = (blockIdx.z >= 1);
    const int KTOT = routed ? II : IS;
    const int NCr  = KTOT / 64;

    extern __shared__ char smem[];
    const uint32_t sbase = smem_u32(smem);
    char* meta = smem + 2 * ASTG_DA + 2 * BSTG_D;
    const __half** rowptr = (const __half**)meta;
    int* aidx = (int*)(meta + 1024);

    int n, off = 0;
    const float* Bb;
    if (routed) {
        int e = blockIdx.z - 1;
        n = g_cnt[e]; off = g_off[e];
        if ((int)(blockIdx.x * 128) >= n) return;
        Bb = w2 + (size_t)e * (size_t)II * H;
    } else { n = T; Bb = sw2; }

    const int row0 = blockIdx.x * 128;
    const int col0 = blockIdx.y * 128;
    const int tid = threadIdx.x;
    const int nv = routed ? min(128, n - row0) : 128;

    if (tid < 128) {
        int gr = row0 + tid;
        int a = -1;
        const __half* p;
        if (!routed) p = g_shh + (size_t)gr * IS;
        else {
            if (gr < n) a = g_alist[off + gr];
            int aa = a >= 0 ? a : g_alist[off];
            p = g_hh + (size_t)aa * II;
        }
        rowptr[tid] = p;
        aidx[tid] = a;
    }
    __syncthreads();

    const int lane = tid & 31, wid = tid >> 5;
    const int wm = wid >> 2, wn = wid & 3;
    const int gg = lane >> 2, t4 = lane & 3;

    float4 bF[8];
    float acc[4][4][4] = {};

    auto cpA = [&](int k0, int s) {
        #pragma unroll
        for (int r = 0; r < 4; r++) {
            int u = tid + 256 * r;
            int m = u >> 3, kq = u & 7;
            cpasync16(sbase + s * ASTG_DA + m * 144 + kq * 16, rowptr[m] + k0 + kq * 8);
        }
    };
    auto ldgB = [&](int k0) {
        #pragma unroll
        for (int r = 0; r < 8; r++) {
            int u = tid + 256 * r;
            int k = u >> 5, ng = u & 31;
            bF[r] = *(const float4*)(Bb + (size_t)(k0 + k) * H + col0 + ng * 4);
        }
    };
    auto stsB = [&](int s) {
        char* B_ = smem + BOFF_D + s * BSTG_D;
        #pragma unroll
        for (int r = 0; r < 8; r++) {
            int u = tid + 256 * r;
            int k = u >> 5, ng = u & 31;
            *(uint2*)(B_ + k * 272 + ng * 8) =
                make_uint2(pk2(bF[r].x, bF[r].y), pk2(bF[r].z, bF[r].w));
        }
    };
    const int lrA = (lane & 7) + ((lane >> 3) & 1) * 8;
    const int lkA = (lane >> 4) * 8;
    const int kBo = (lane & 7) + ((lane >> 3) & 1) * 8;
    const int nBo = (lane >> 4) * 8;
    auto comp = [&](int s) {
        const uint32_t Ab = sbase + s * ASTG_DA;
        const uint32_t Bbs = sbase + BOFF_D + s * BSTG_D;
        if (wm * 64 >= nv) return;
        #pragma unroll
        for (int ks = 0; ks < 4; ks++) {
            const int kh = ks * 16;
            uint32_t af[4][4];
            #pragma unroll
            for (int mt = 0; mt < 4; mt++)
                if (wm * 64 + mt * 16 < nv)
                    ldmx4(af[mt], Ab + (wm * 64 + mt * 16 + lrA) * 144 + (kh + lkA) * 2);
            uint32_t bf[2][4];
            #pragma unroll
            for (int np = 0; np < 2; np++)
                ldmx4t(bf[np], Bbs + (kh + kBo) * 272 + (wn * 32 + np * 16 + nBo) * 2);
            #pragma unroll
            for (int mt = 0; mt < 4; mt++) {
                if (wm * 64 + mt * 16 >= nv) continue;
                #pragma unroll
                for (int nt = 0; nt < 4; nt++)
                    mma16(acc[mt][nt], af[mt], bf[nt >> 1][(nt & 1) * 2], bf[nt >> 1][(nt & 1) * 2 + 1]);
            }
        }
    };

    cpA(0, 0); cp_commit();
    ldgB(0);
    stsB(0);
    cp_wait0();
    __syncthreads();
    for (int c = 0; c < NCr; c++) {
        if (c + 1 < NCr) {
            cpA((c + 1) * 64, (c + 1) & 1); cp_commit();
            ldgB((c + 1) * 64);
        }
        comp(c & 1);
        if (c + 1 < NCr) stsB((c + 1) & 1);
        cp_wait0();
        __syncthreads();
    }

    const float scale = routed ? SCALEF : 1.f;
    #pragma unroll
    for (int mt = 0; mt < 4; mt++) {
        #pragma unroll
        for (int hf = 0; hf < 2; hf++) {
            int r = wm * 64 + mt * 16 + gg + hf * 8;
            float* drow = nullptr;
            if (!routed) drow = Dout + (size_t)(row0 + r) * H + col0;
            else {
                int a = aidx[r];
                if (a >= 0) drow = Dout + (size_t)(a / KSEL) * H + col0;
            }
            if (drow) {
                #pragma unroll
                for (int nt = 0; nt < 4; nt++) {
                    int cc = wn * 32 + nt * 8 + t4 * 2;
                    atomicAdd(drow + cc,     scale * acc[mt][nt][hf * 2]);
                    atomicAdd(drow + cc + 1, scale * acc[mt][nt][hf * 2 + 1]);
                }
            }
        }
    }
}

// ---------------- launch ----------------
extern "C" void kernel_launch(void* const* d_in, const int* in_sizes, int n_in,
                              void* d_out, int out_size) {
    const float* x   = (const float*)d_in[0];
    const float* gw  = (const float*)d_in[1];
    const float* gb  = (const float*)d_in[2];
    const float* w1  = (const float*)d_in[3];
    const float* w2  = (const float*)d_in[4];
    const float* sw1 = (const float*)d_in[5];
    const float* sw2 = (const float*)d_in[6];
    float* out = (float*)d_out;

    cudaFuncSetAttribute(gemm_gateup, cudaFuncAttributeMaxDynamicSharedMemorySize, SMEM_F);
    cudaFuncSetAttribute(gemm_down,   cudaFuncAttributeMaxDynamicSharedMemorySize, SMEM_D);

    xhalf_kernel<<<((T * H / 4) + 255) / 256, 256>>>(x, out);
    router_kernel<<<T, 128>>>(x, gw, gb);
    fill_kernel<<<(NA + 255) / 256, 256>>>();

    // merged gate_up: z 0-1 = shared expert halves (first), z>=2 routed expert z-2
    gemm_gateup<<<dim3(16, 11, E + 2), 256, SMEM_F>>>(w1, sw1);
    // merged down-proj: z==0 shared (longest, first), z>=1 routed expert z-1
    gemm_down<<<dim3(16, H / 128, E + 1), 256, SMEM_D>>>(w2, sw2, out);
}

// round 16
// speedup vs baseline: 1.6654x; 1.4677x over previous
#include <cuda_runtime.h>
#include <cuda_fp16.h>
#include <math.h>
#include <stdint.h>

#define T 2048
#define H 2048
#define E 32
#define KSEL 6
#define G 8
#define TOPKG 4
#define II 1408
#define IS 2816
#define SCALEF 2.5f
#define NA (T*KSEL)   // 12288 assignments

// ---------------- scratch (allocation-free: __device__ globals) ----------------
__device__ float    g_topk_w[NA];
__device__ int      g_topk_id[NA];
__device__ int      g_cnt[E];
__device__ int      g_off[E];
__device__ int      g_cur[E];
__device__ int      g_alist[NA];
__device__ unsigned g_done;
__device__ __half   g_xh[(size_t)T * H];        // x in fp16 (8 MB)
__device__ __half   g_hh[(size_t)NA * II];      // routed hidden fp16 (~35 MB)
__device__ __half   g_shh[(size_t)T * IS];      // shared hidden fp16 (~12 MB)

// ---------------- helpers ----------------
__device__ __forceinline__ uint32_t smem_u32(const void* p) {
    uint32_t a;
    asm("{ .reg .u64 t; cvta.to.shared.u64 t, %1; cvt.u32.u64 %0, t; }" : "=r"(a) : "l"(p));
    return a;
}
__device__ __forceinline__ uint32_t pk2(float a, float b) {
    __half2 h = __floats2half2_rn(a, b);
    return *(uint32_t*)&h;
}
__device__ __forceinline__ void cpasync16(uint32_t dst, const void* src) {
    asm volatile("cp.async.cg.shared.global [%0], [%1], 16;" :: "r"(dst), "l"(src));
}
__device__ __forceinline__ void cp_commit() {
    asm volatile("cp.async.commit_group;" ::: "memory");
}
__device__ __forceinline__ void cp_wait0() {
    asm volatile("cp.async.wait_group 0;" ::: "memory");
}
__device__ __forceinline__ void ldmx4(uint32_t* r, uint32_t addr) {
    asm volatile("ldmatrix.sync.aligned.m8n8.x4.shared.b16 {%0,%1,%2,%3}, [%4];"
                 : "=r"(r[0]), "=r"(r[1]), "=r"(r[2]), "=r"(r[3]) : "r"(addr));
}
__device__ __forceinline__ void ldmx4t(uint32_t* r, uint32_t addr) {
    asm volatile("ldmatrix.sync.aligned.m8n8.x4.trans.shared.b16 {%0,%1,%2,%3}, [%4];"
                 : "=r"(r[0]), "=r"(r[1]), "=r"(r[2]), "=r"(r[3]) : "r"(addr));
}
__device__ __forceinline__ void mma16(float* d, const uint32_t* a, uint32_t b0, uint32_t b1) {
    asm volatile(
        "mma.sync.aligned.m16n8k16.row.col.f32.f16.f16.f32 "
        "{%0,%1,%2,%3}, {%4,%5,%6,%7}, {%8,%9}, {%0,%1,%2,%3};"
        : "+f"(d[0]), "+f"(d[1]), "+f"(d[2]), "+f"(d[3])
        : "r"(a[0]), "r"(a[1]), "r"(a[2]), "r"(a[3]), "r"(b0), "r"(b1));
}
__device__ __forceinline__ float silu_fast(float g) { return g / (1.f + __expf(-g)); }

// ---------------- small kernels ----------------
__global__ void xhalf_kernel(const float* __restrict__ x, float* __restrict__ out) {
    int idx = blockIdx.x * blockDim.x + threadIdx.x;
    if (blockIdx.x == 0 && threadIdx.x < E) g_cnt[threadIdx.x] = 0;
    if (blockIdx.x == 0 && threadIdx.x == 0) g_done = 0;
    if (idx >= (T * H) / 4) return;
    float4 v = *(const float4*)(x + (size_t)idx * 4);
    uint2 o = make_uint2(pk2(v.x, v.y), pk2(v.z, v.w));
    *(uint2*)(g_xh + (size_t)idx * 4) = o;
    *(float4*)(out + (size_t)idx * 4) = make_float4(0.f, 0.f, 0.f, 0.f);
}

__global__ void router_kernel(const float* __restrict__ x,
                              const float* __restrict__ gw,
                              const float* __restrict__ gb) {
    int t = blockIdx.x;
    __shared__ float xs[H];
    __shared__ float logit[E];
    for (int i = threadIdx.x; i < H; i += blockDim.x) xs[i] = x[(size_t)t * H + i];
    __syncthreads();
    int warp = threadIdx.x >> 5, lane = threadIdx.x & 31;
    for (int e = warp; e < E; e += 4) {
        const float* w = gw + (size_t)e * H;
        float s = 0.f;
        for (int i = lane; i < H; i += 32) s += xs[i] * w[i];
        #pragma unroll
        for (int o = 16; o; o >>= 1) s += __shfl_xor_sync(0xffffffffu, s, o);
        if (lane == 0) logit[e] = s;
    }
    __syncthreads();
    if (threadIdx.x == 0) {
        float sc[E], ss[E];
        #pragma unroll
        for (int e = 0; e < E; e++) {
            float s = 1.f / (1.f + expf(-logit[e]));
            ss[e] = s;
            sc[e] = s + gb[e];
        }
        float gsc[G];
        #pragma unroll
        for (int g = 0; g < G; g++) {
            float m1 = -1e30f, m2 = -1e30f;
            #pragma unroll
            for (int j = 0; j < 4; j++) {
                float v = sc[g * 4 + j];
                if (v > m1) { m2 = m1; m1 = v; } else if (v > m2) m2 = v;
            }
            gsc[g] = m1 + m2;
        }
        bool gsel[G];
        #pragma unroll
        for (int g = 0; g < G; g++) gsel[g] = false;
        for (int r = 0; r < TOPKG; r++) {
            int best = -1; float bv = -1e30f;
            for (int g = 0; g < G; g++)
                if (!gsel[g] && gsc[g] > bv) { bv = gsc[g]; best = g; }
            gsel[best] = true;
        }
        bool esel[E];
        #pragma unroll
        for (int e = 0; e < E; e++) esel[e] = false;
        int ids[KSEL];
        for (int r = 0; r < KSEL; r++) {
            int best = -1; float bv = -1e30f;
            for (int e = 0; e < E; e++) {
                if (esel[e] || !gsel[e >> 2]) continue;
                if (sc[e] > bv) { bv = sc[e]; best = e; }
            }
            esel[best] = true; ids[r] = best;
        }
        float w[KSEL], wsum = 0.f;
        for (int r = 0; r < KSEL; r++) { w[r] = ss[ids[r]]; wsum += w[r]; }
        float inv = 1.f / wsum;
        for (int r = 0; r < KSEL; r++) {
            g_topk_w[t * KSEL + r] = w[r] * inv;
            g_topk_id[t * KSEL + r] = ids[r];
            atomicAdd(&g_cnt[ids[r]], 1);
        }
        __threadfence();
        unsigned prev = atomicAdd(&g_done, 1u);
        if (prev == gridDim.x - 1) {
            int run = 0;
            for (int e = 0; e < E; e++) {
                g_off[e] = run;
                g_cur[e] = run;
                run += g_cnt[e];
            }
        }
    }
}

__global__ void fill_kernel() {
    int a = blockIdx.x * blockDim.x + threadIdx.x;
    if (a >= NA) return;
    int e = g_topk_id[a];
    int pos = atomicAdd(&g_cur[e], 1);
    g_alist[pos] = a;
}

// =====================================================================
// MERGED gate_up GEMM + silu*mul(*wt) -> fp16 hidden. (R9 config)
// blockIdx.z in [0,32]: z<32 routed expert z, z==32 shared expert.
// B smem [k][n] (272B stride) + ldmatrix.trans. Block 128x128; K-chunk 32.
// =====================================================================
#define ASTG_FA 10240        // A stage: 128 * 80
#define BSTG_F  17408        // B stage: 2 tiles * 32 * 272
#define BOFF_F  (2*ASTG_FA)
#define SMEM_F  (2*ASTG_FA + 2*BSTG_F + 2048)

__global__ void __launch_bounds__(256, 1)
gemm_gateup(const float* __restrict__ w1, const float* __restrict__ sw1)
{
    const bool routed = (blockIdx.z < 32);
    const int NPER = routed ? II : IS;
    const int LDB  = 2 * NPER;
    constexpr int NC = H / 32;

    if ((int)(blockIdx.y * 128) >= NPER) return;

    extern __shared__ char smem[];
    const uint32_t sbase = smem_u32(smem);
    char* meta = smem + 2 * ASTG_FA + 2 * BSTG_F;
    const __half** rowptr = (const __half**)meta;     // 128 ptrs
    int* aidx = (int*)(meta + 1024);                  // 128 ints

    int n, off = 0;
    const float* Bb;
    if (routed) {
        int e = blockIdx.z;
        n = g_cnt[e]; off = g_off[e];
        if ((int)(blockIdx.x * 128) >= n) return;
        Bb = w1 + (size_t)e * (size_t)H * (2 * II);
    } else { n = T; Bb = sw1; }

    const int row0 = blockIdx.x * 128;
    const int col0 = blockIdx.y * 128;
    const int tid = threadIdx.x;
    const int nv = routed ? min(128, n - row0) : 128;

    if (tid < 128) {
        int gr = row0 + tid;
        int a = -1;
        if (routed && gr < n) a = g_alist[off + gr];
        int aa = (!routed) ? gr : ((a >= 0 ? a : g_alist[off]) / KSEL);
        rowptr[tid] = g_xh + (size_t)aa * H;
        aidx[tid] = a;
    }
    __syncthreads();

    const int lane = tid & 31, wid = tid >> 5;
    const int wm = wid >> 2, wn = wid & 3;
    const int gg = lane >> 2, t4 = lane & 3;

    float4 bF[8];
    float accg[4][4][4] = {}, accu[4][4][4] = {};

    auto cpA = [&](int k0, int s) {
        #pragma unroll
        for (int r = 0; r < 2; r++) {
            int u = tid + 256 * r;
            int m = u >> 2, kq = u & 3;
            cpasync16(sbase + s * ASTG_FA + m * 80 + kq * 16, rowptr[m] + k0 + kq * 8);
        }
    };
    auto ldgB = [&](int k0) {
        #pragma unroll
        for (int r = 0; r < 8; r++) {
            int u = tid + 256 * r;
            int tile = u >> 10;            // 0 = gate, 1 = up
            int k = (u >> 5) & 31, ng = u & 31;
            const float* gp = Bb + (size_t)(k0 + k) * LDB + tile * NPER + col0 + ng * 4;
            bF[r] = *(const float4*)gp;
        }
    };
    auto stsB = [&](int s) {
        char* B_ = smem + BOFF_F + s * BSTG_F;
        #pragma unroll
        for (int r = 0; r < 8; r++) {
            int u = tid + 256 * r;
            int tile = u >> 10;
            int k = (u >> 5) & 31, ng = u & 31;
            *(uint2*)(B_ + tile * 8704 + k * 272 + ng * 8) =
                make_uint2(pk2(bF[r].x, bF[r].y), pk2(bF[r].z, bF[r].w));
        }
    };
    const int lrA = (lane & 7) + ((lane >> 3) & 1) * 8;
    const int lkA = (lane >> 4) * 8;
    const int kBo = (lane & 7) + ((lane >> 3) & 1) * 8;
    const int nBo = (lane >> 4) * 8;
    auto comp = [&](int s) {
        const uint32_t Ab = sbase + s * ASTG_FA;
        const uint32_t Bgb = sbase + BOFF_F + s * BSTG_F;
        const uint32_t Bub = Bgb + 8704;
        if (wm * 64 >= nv) return;
        #pragma unroll
        for (int ks = 0; ks < 2; ks++) {
            const int kh = ks * 16;
            uint32_t af[4][4];
            #pragma unroll
            for (int mt = 0; mt < 4; mt++)
                if (wm * 64 + mt * 16 < nv)
                    ldmx4(af[mt], Ab + (wm * 64 + mt * 16 + lrA) * 80 + (kh + lkA) * 2);
            uint32_t bfg[2][4], bfu[2][4];
            #pragma unroll
            for (int np = 0; np < 2; np++) {
                uint32_t co = (wn * 32 + np * 16 + nBo) * 2;
                ldmx4t(bfg[np], Bgb + (kh + kBo) * 272 + co);
                ldmx4t(bfu[np], Bub + (kh + kBo) * 272 + co);
            }
            #pragma unroll
            for (int mt = 0; mt < 4; mt++) {
                if (wm * 64 + mt * 16 >= nv) continue;
                #pragma unroll
                for (int nt = 0; nt < 4; nt++) {
                    mma16(accg[mt][nt], af[mt], bfg[nt >> 1][(nt & 1) * 2], bfg[nt >> 1][(nt & 1) * 2 + 1]);
                    mma16(accu[mt][nt], af[mt], bfu[nt >> 1][(nt & 1) * 2], bfu[nt >> 1][(nt & 1) * 2 + 1]);
                }
            }
        }
    };

    cpA(0, 0); cp_commit();
    ldgB(0);
    stsB(0);
    cp_wait0();
    __syncthreads();
    for (int c = 0; c < NC; c++) {
        if (c + 1 < NC) {
            cpA((c + 1) * 32, (c + 1) & 1); cp_commit();
            ldgB((c + 1) * 32);
        }
        comp(c & 1);
        if (c + 1 < NC) stsB((c + 1) & 1);
        cp_wait0();
        __syncthreads();
    }

    // epilogue: h = silu(g)*u*wt  -> fp16
    #pragma unroll
    for (int mt = 0; mt < 4; mt++) {
        #pragma unroll
        for (int hf = 0; hf < 2; hf++) {
            int r = wm * 64 + mt * 16 + gg + hf * 8;
            __half* drow = nullptr;
            float wt = 1.f;
            if (!routed) drow = g_shh + (size_t)(row0 + r) * IS + col0;
            else {
                int a = aidx[r];
                if (a >= 0) { drow = g_hh + (size_t)a * II + col0; wt = g_topk_w[a]; }
            }
            if (drow) {
                #pragma unroll
                for (int nt = 0; nt < 4; nt++) {
                    int cc = wn * 32 + nt * 8 + t4 * 2;
                    float g0 = accg[mt][nt][hf * 2],     u0 = accu[mt][nt][hf * 2];
                    float g1 = accg[mt][nt][hf * 2 + 1], u1 = accu[mt][nt][hf * 2 + 1];
                    *(__half2*)(drow + cc) = __floats2half2_rn(silu_fast(g0) * u0 * wt, silu_fast(g1) * u1 * wt);
                }
            }
        }
    }
}

// =====================================================================
// MERGED down-proj GEMM: z<32 routed (K=II), z==32 shared (K=IS).
// out pre-zeroed; both paths atomicAdd (routed scaled by 2.5).
// Block 128x128, K-chunk 64.  (R9 config)
// =====================================================================
#define ASTG_DA 18432        // A stage: 128 * 144
#define BSTG_D  17408        // B stage: 64 * 272
#define BOFF_D  (2*ASTG_DA)
#define SMEM_D  (2*ASTG_DA + 2*BSTG_D + 2048)

__global__ void __launch_bounds__(256, 1)
gemm_down(const float* __restrict__ w2, const float* __restrict__ sw2, float* __restrict__ Dout)
{
    const bool routed = (blockIdx.z < 32);
    const int KTOT = routed ? II : IS;
    const int NCr  = KTOT / 64;

    extern __shared__ char smem[];
    const uint32_t sbase = smem_u32(smem);
    char* meta = smem + 2 * ASTG_DA + 2 * BSTG_D;
    const __half** rowptr = (const __half**)meta;
    int* aidx = (int*)(meta + 1024);

    int n, off = 0;
    const float* Bb;
    if (routed) {
        int e = blockIdx.z;
        n = g_cnt[e]; off = g_off[e];
        if ((int)(blockIdx.x * 128) >= n) return;
        Bb = w2 + (size_t)e * (size_t)II * H;
    } else { n = T; Bb = sw2; }

    const int row0 = blockIdx.x * 128;
    const int col0 = blockIdx.y * 128;
    const int tid = threadIdx.x;
    const int nv = routed ? min(128, n - row0) : 128;

    if (tid < 128) {
        int gr = row0 + tid;
        int a = -1;
        const __half* p;
        if (!routed) p = g_shh + (size_t)gr * IS;
        else {
            if (gr < n) a = g_alist[off + gr];
            int aa = a >= 0 ? a : g_alist[off];
            p = g_hh + (size_t)aa * II;
        }
        rowptr[tid] = p;
        aidx[tid] = a;
    }
    __syncthreads();

    const int lane = tid & 31, wid = tid >> 5;
    const int wm = wid >> 2, wn = wid & 3;
    const int gg = lane >> 2, t4 = lane & 3;

    float4 bF[8];
    float acc[4][4][4] = {};

    auto cpA = [&](int k0, int s) {
        #pragma unroll
        for (int r = 0; r < 4; r++) {
            int u = tid + 256 * r;
            int m = u >> 3, kq = u & 7;
            cpasync16(sbase + s * ASTG_DA + m * 144 + kq * 16, rowptr[m] + k0 + kq * 8);
        }
    };
    auto ldgB = [&](int k0) {
        #pragma unroll
        for (int r = 0; r < 8; r++) {
            int u = tid + 256 * r;
            int k = u >> 5, ng = u & 31;
            bF[r] = *(const float4*)(Bb + (size_t)(k0 + k) * H + col0 + ng * 4);
        }
    };
    auto stsB = [&](int s) {
        char* B_ = smem + BOFF_D + s * BSTG_D;
        #pragma unroll
        for (int r = 0; r < 8; r++) {
            int u = tid + 256 * r;
            int k = u >> 5, ng = u & 31;
            *(uint2*)(B_ + k * 272 + ng * 8) =
                make_uint2(pk2(bF[r].x, bF[r].y), pk2(bF[r].z, bF[r].w));
        }
    };
    const int lrA = (lane & 7) + ((lane >> 3) & 1) * 8;
    const int lkA = (lane >> 4) * 8;
    const int kBo = (lane & 7) + ((lane >> 3) & 1) * 8;
    const int nBo = (lane >> 4) * 8;
    auto comp = [&](int s) {
        const uint32_t Ab = sbase + s * ASTG_DA;
        const uint32_t Bbs = sbase + BOFF_D + s * BSTG_D;
        if (wm * 64 >= nv) return;
        #pragma unroll
        for (int ks = 0; ks < 4; ks++) {
            const int kh = ks * 16;
            uint32_t af[4][4];
            #pragma unroll
            for (int mt = 0; mt < 4; mt++)
                if (wm * 64 + mt * 16 < nv)
                    ldmx4(af[mt], Ab + (wm * 64 + mt * 16 + lrA) * 144 + (kh + lkA) * 2);
            uint32_t bf[2][4];
            #pragma unroll
            for (int np = 0; np < 2; np++)
                ldmx4t(bf[np], Bbs + (kh + kBo) * 272 + (wn * 32 + np * 16 + nBo) * 2);
            #pragma unroll
            for (int mt = 0; mt < 4; mt++) {
                if (wm * 64 + mt * 16 >= nv) continue;
                #pragma unroll
                for (int nt = 0; nt < 4; nt++)
                    mma16(acc[mt][nt], af[mt], bf[nt >> 1][(nt & 1) * 2], bf[nt >> 1][(nt & 1) * 2 + 1]);
            }
        }
    };

    cpA(0, 0); cp_commit();
    ldgB(0);
    stsB(0);
    cp_wait0();
    __syncthreads();
    for (int c = 0; c < NCr; c++) {
        if (c + 1 < NCr) {
            cpA((c + 1) * 64, (c + 1) & 1); cp_commit();
            ldgB((c + 1) * 64);
        }
        comp(c & 1);
        if (c + 1 < NCr) stsB((c + 1) & 1);
        cp_wait0();
        __syncthreads();
    }

    const float scale = routed ? SCALEF : 1.f;
    #pragma unroll
    for (int mt = 0; mt < 4; mt++) {
        #pragma unroll
        for (int hf = 0; hf < 2; hf++) {
            int r = wm * 64 + mt * 16 + gg + hf * 8;
            float* drow = nullptr;
            if (!routed) drow = Dout + (size_t)(row0 + r) * H + col0;
            else {
                int a = aidx[r];
                if (a >= 0) drow = Dout + (size_t)(a / KSEL) * H + col0;
            }
            if (drow) {
                #pragma unroll
                for (int nt = 0; nt < 4; nt++) {
                    int cc = wn * 32 + nt * 8 + t4 * 2;
                    atomicAdd(drow + cc,     scale * acc[mt][nt][hf * 2]);
                    atomicAdd(drow + cc + 1, scale * acc[mt][nt][hf * 2 + 1]);
                }
            }
        }
    }
}

// ---------------- launch ----------------
extern "C" void kernel_launch(void* const* d_in, const int* in_sizes, int n_in,
                              void* d_out, int out_size) {
    const float* x   = (const float*)d_in[0];
    const float* gw  = (const float*)d_in[1];
    const float* gb  = (const float*)d_in[2];
    const float* w1  = (const float*)d_in[3];
    const float* w2  = (const float*)d_in[4];
    const float* sw1 = (const float*)d_in[5];
    const float* sw2 = (const float*)d_in[6];
    float* out = (float*)d_out;

    cudaFuncSetAttribute(gemm_gateup, cudaFuncAttributeMaxDynamicSharedMemorySize, SMEM_F);
    cudaFuncSetAttribute(gemm_down,   cudaFuncAttributeMaxDynamicSharedMemorySize, SMEM_D);

    xhalf_kernel<<<((T * H / 4) + 255) / 256, 256>>>(x, out);
    router_kernel<<<T, 128>>>(x, gw, gb);
    fill_kernel<<<(NA + 255) / 256, 256>>>();

    // merged gate_up: z<32 routed experts, z==32 shared expert
    gemm_gateup<<<dim3(16, IS / 128, E + 1), 256, SMEM_F>>>(w1, sw1);
    // merged down-proj: all paths atomicAdd into pre-zeroed out
    gemm_down<<<dim3(16, H / 128, E + 1), 256, SMEM_D>>>(w2, sw2, out);
}